// round 16
// baseline (speedup 1.0000x reference)
#include <cuda_runtime.h>
#include <cuda_fp16.h>
#include <cstdint>

#define N_NODES 50000
#define N_EDGES 800000
#define DIM 96
#define KTOT 192
#define CAP 64   // bucket capacity per node (avg degree 16)

// ---------------------------------------------------------------------------
// Scratch (__device__ globals per allocation-free rule)
// ---------------------------------------------------------------------------
__device__ __align__(128) __half g_ah[N_NODES * KTOT];  // [xh | mean_h], 19.2MB
__device__ __align__(128) __half g_wh[DIM * KTOT];      // B fp16 [n][k]
__device__ __align__(128) float g_agg[N_NODES * DIM];   // raw sums (ovf rows)
__device__ int g_cnt[N_NODES];
__device__ int g_bucket[N_NODES * CAP];                 // 12.8 MB
__device__ int g_ctl[2];                                // [0]=novf, [1]=done
__device__ int g_ovf[N_EDGES * 2];

// ---------------------------------------------------------------------------
// Fused prep: convert x -> fp16 (g_ah cols 0..95), [Ws|Wn] -> g_wh,
// and bucket the edges — disjoint thread ranges, one launch.
// ---------------------------------------------------------------------------
#define NXH2 (N_NODES * 48)       // half2 items for x
#define NWH2 (DIM * 48)           // half2 items per weight matrix
#define PREP_TOTAL (NXH2 + NWH2 + N_EDGES)

__global__ void prep_kernel(const float* __restrict__ x,
                            const float* __restrict__ Ws,
                            const float* __restrict__ Wn,
                            const int* __restrict__ ei) {
    int t = blockIdx.x * blockDim.x + threadIdx.x;
    if (t < NXH2) {
        int row = t / 48, j2 = t % 48;
        float2 v = ((const float2*)x)[t];
        ((__half2*)g_ah)[row * 96 + j2] = __floats2half2_rn(v.x, v.y);
    } else if (t < NXH2 + NWH2) {
        int u = t - NXH2;
        int j = u / 48, kp = u % 48;
        float2 a = ((const float2*)Ws)[u];
        float2 b = ((const float2*)Wn)[u];
        ((__half2*)g_wh)[j * 96 + kp]      = __floats2half2_rn(a.x, a.y);
        ((__half2*)g_wh)[j * 96 + 48 + kp] = __floats2half2_rn(b.x, b.y);
    } else if (t < PREP_TOTAL) {
        int e = t - NXH2 - NWH2;
        int src = __ldg(&ei[e]);
        int dst = __ldg(&ei[N_EDGES + e]);
        int slot = atomicAdd(&g_cnt[dst], 1);
        if (slot < CAP) {
            g_bucket[dst * CAP + slot] = src;
        } else {
            int o = atomicAdd(&g_ctl[0], 1);
            g_ovf[2 * o + 0] = src;
            g_ovf[2 * o + 1] = dst;
        }
    }
}

// ---------------------------------------------------------------------------
// Gather: 24 threads/node (8 nodes per 192-thread block). Thread owns 4
// features; per neighbor one uint2 (4 fp16) load; bucket read via int4.
// Fast path (deg<=CAP): writes normalized fp16 mean directly to g_ah.
// Overflow rows: raw fp32 sums to g_agg; the LAST block to finish runs the
// overflow fix inline (no separate kernel launch).
// ---------------------------------------------------------------------------
#define GATHER_BLOCKS ((N_NODES + 7) / 8)   // 6250

__global__ void gather_kernel(const float* __restrict__ x) {
    int node = blockIdx.x * 8 + (threadIdx.x / 24);
    int j4 = threadIdx.x % 24;          // uint2 (4-half) index 0..23
    bool active = (node < N_NODES);

    if (active) {
        int deg = g_cnt[node];
        int n = (deg < CAP) ? deg : CAP;
        const int* __restrict__ b = g_bucket + node * CAP;
        const uint2* __restrict__ xh4 = (const uint2*)g_ah;   // row = 48 uint2

        float ax = 0.f, ay = 0.f, az = 0.f, aw = 0.f;
        int s = 0;
        for (; s + 4 <= n; s += 4) {
            int4 b4 = __ldg((const int4*)(b + s));
            uint2 v0 = __ldg(&xh4[b4.x * 48 + j4]);
            uint2 v1 = __ldg(&xh4[b4.y * 48 + j4]);
            uint2 v2 = __ldg(&xh4[b4.z * 48 + j4]);
            uint2 v3 = __ldg(&xh4[b4.w * 48 + j4]);
            float2 p0 = __half22float2(*(__half2*)&v0.x);
            float2 q0 = __half22float2(*(__half2*)&v0.y);
            float2 p1 = __half22float2(*(__half2*)&v1.x);
            float2 q1 = __half22float2(*(__half2*)&v1.y);
            float2 p2 = __half22float2(*(__half2*)&v2.x);
            float2 q2 = __half22float2(*(__half2*)&v2.y);
            float2 p3 = __half22float2(*(__half2*)&v3.x);
            float2 q3 = __half22float2(*(__half2*)&v3.y);
            ax += (p0.x + p1.x) + (p2.x + p3.x);
            ay += (p0.y + p1.y) + (p2.y + p3.y);
            az += (q0.x + q1.x) + (q2.x + q3.x);
            aw += (q0.y + q1.y) + (q2.y + q3.y);
        }
        for (; s < n; s++) {
            int sn = __ldg(&b[s]);
            uint2 v = __ldg(&xh4[sn * 48 + j4]);
            float2 p = __half22float2(*(__half2*)&v.x);
            float2 q = __half22float2(*(__half2*)&v.y);
            ax += p.x; ay += p.y; az += q.x; aw += q.y;
        }

        if (deg <= CAP) {
            float inv = 1.0f / (float)((deg > 1) ? deg : 1);
            __half2 h0 = __floats2half2_rn(ax * inv, ay * inv);
            __half2 h1 = __floats2half2_rn(az * inv, aw * inv);
            uint2 o;
            o.x = *(uint32_t*)&h0;
            o.y = *(uint32_t*)&h1;
            ((uint2*)g_ah)[node * 48 + 24 + j4] = o;
        } else {
            float4 o = make_float4(ax, ay, az, aw);
            ((float4*)g_agg)[node * 24 + j4] = o;
        }
    }

    // ---- last-block-done overflow fix (usually zero work) ----
    __shared__ int sIsLast;
    __threadfence();
    __syncthreads();
    if (threadIdx.x == 0) {
        int done = atomicAdd(&g_ctl[1], 1);
        sIsLast = (done == GATHER_BLOCKS - 1) ? 1 : 0;
    }
    __syncthreads();
    if (!sIsLast) return;

    int nov = g_ctl[0];
    if (nov == 0) return;
    int total = nov * 24;
    for (int t = threadIdx.x; t < total; t += blockDim.x) {
        int e = t / 24, c = t % 24;
        int src = g_ovf[2 * e + 0];
        int dst = g_ovf[2 * e + 1];
        float4 v = ((const float4*)(x + (size_t)src * DIM))[c];
        float* p = g_agg + (size_t)dst * DIM + c * 4;
        asm volatile("red.global.add.v4.f32 [%0], {%1,%2,%3,%4};"
                     :: "l"(p), "f"(v.x), "f"(v.y), "f"(v.z), "f"(v.w)
                     : "memory");
    }
    __threadfence();
    __syncthreads();
    for (int t = threadIdx.x; t < total; t += blockDim.x) {
        int e = t / 24, c = t % 24;
        int dst = g_ovf[2 * e + 1];
        float inv = 1.0f / (float)g_cnt[dst];
        float4 v = ((const float4*)g_agg)[dst * 24 + c];
        __half2 h0 = __floats2half2_rn(v.x * inv, v.y * inv);
        __half2 h1 = __floats2half2_rn(v.z * inv, v.w * inv);
        uint2 o;
        o.x = *(uint32_t*)&h0;
        o.y = *(uint32_t*)&h1;
        ((uint2*)g_ah)[dst * 48 + 24 + c] = o;
    }
}

// ---------------------------------------------------------------------------
// HMMA GEMM: out[50000,96] = g_ah[50000,192] @ g_wh[96,192]^T + (bs+bn)
// BM=128 rows/block, 8 warps (256 threads); warp = 16 rows x 96 cols
// = 12 m16n8k16 tiles. Smem pitch 200 halves -> conflict-free ldmatrix.
// ---------------------------------------------------------------------------
#define HBM 128
#define HPITCH 200
#define HMMA_THREADS 256
#define HMMA_BLOCKS ((N_NODES + HBM - 1) / HBM)   // 391
#define HMMA_SMEM ((HBM + DIM) * HPITCH * 2)      // 89600 bytes

__device__ __forceinline__ uint32_t smem_u32(const void* p) {
    return (uint32_t)__cvta_generic_to_shared(p);
}
__device__ __forceinline__ void ldsm_x4(uint32_t& r0, uint32_t& r1,
                                        uint32_t& r2, uint32_t& r3,
                                        uint32_t addr) {
    asm volatile("ldmatrix.sync.aligned.m8n8.x4.shared.b16 {%0,%1,%2,%3}, [%4];"
                 : "=r"(r0), "=r"(r1), "=r"(r2), "=r"(r3) : "r"(addr));
}
__device__ __forceinline__ void mma16816(float* d, const uint32_t* a,
                                         const uint32_t* b) {
    asm volatile(
        "mma.sync.aligned.m16n8k16.row.col.f32.f16.f16.f32 "
        "{%0,%1,%2,%3}, {%4,%5,%6,%7}, {%8,%9}, {%0,%1,%2,%3};"
        : "+f"(d[0]), "+f"(d[1]), "+f"(d[2]), "+f"(d[3])
        : "r"(a[0]), "r"(a[1]), "r"(a[2]), "r"(a[3]), "r"(b[0]), "r"(b[1]));
}

__global__ __launch_bounds__(HMMA_THREADS)
void hmma_kernel(const float* __restrict__ bs, const float* __restrict__ bn,
                 float* __restrict__ out) {
    extern __shared__ __half hsm[];
    __half* sA = hsm;                      // [HBM][HPITCH]
    __half* sB = hsm + HBM * HPITCH;       // [DIM][HPITCH]
    __shared__ float sBias[DIM];

    const int tid = threadIdx.x;
    const int warp = tid >> 5;
    const int lane = tid & 31;
    const int rowBase = blockIdx.x * HBM;

    if (tid < DIM) sBias[tid] = bs[tid] + bn[tid];

    // Load A: 128 rows x 24 uint4 = 3072 (12/thread).
    #pragma unroll
    for (int it = 0; it < 12; it++) {
        int idx = it * HMMA_THREADS + tid;
        int m = idx / 24, q = idx % 24;
        int row = rowBase + m;
        uint4 v = make_uint4(0u, 0u, 0u, 0u);
        if (row < N_NODES)
            v = ((const uint4*)(g_ah + (size_t)row * KTOT))[q];
        *(uint4*)&sA[m * HPITCH + q * 8] = v;
    }
    // Load B: 96 rows x 24 uint4 = 2304 (9/thread).
    #pragma unroll
    for (int it = 0; it < 9; it++) {
        int idx = it * HMMA_THREADS + tid;
        int j = idx / 24, q = idx % 24;
        *(uint4*)&sB[j * HPITCH + q * 8] = ((const uint4*)(g_wh + j * KTOT))[q];
    }
    __syncthreads();

    float acc[12][4];
    #pragma unroll
    for (int nt = 0; nt < 12; nt++)
        #pragma unroll
        for (int i = 0; i < 4; i++) acc[nt][i] = 0.0f;

    const int mrow0 = warp * 16;

    #pragma unroll 3
    for (int k16 = 0; k16 < KTOT / 16; k16++) {
        int k0 = k16 * 16;
        uint32_t a[4];
        {
            uint32_t addr = smem_u32(
                &sA[(mrow0 + (lane & 15)) * HPITCH + k0 + ((lane >> 4) << 3)]);
            ldsm_x4(a[0], a[1], a[2], a[3], addr);
        }
        uint32_t b[12][2];
        #pragma unroll
        for (int np = 0; np < 6; np++) {
            int n0 = np * 16;
            int nrow = n0 + ((lane >> 4) << 3) + (lane & 7);
            int kcol = k0 + (((lane >> 3) & 1) << 3);
            uint32_t addr = smem_u32(&sB[nrow * HPITCH + kcol]);
            uint32_t r0, r1, r2, r3;
            ldsm_x4(r0, r1, r2, r3, addr);
            b[2 * np + 0][0] = r0; b[2 * np + 0][1] = r1;
            b[2 * np + 1][0] = r2; b[2 * np + 1][1] = r3;
        }
        #pragma unroll
        for (int nt = 0; nt < 12; nt++)
            mma16816(acc[nt], a, b[nt]);
    }

    // Epilogue: lane l -> rows l/4 and l/4+8, cols (l%4)*2, +1.
    int r0 = rowBase + mrow0 + (lane >> 2);
    int r1 = r0 + 8;
    #pragma unroll
    for (int nt = 0; nt < 12; nt++) {
        int c = nt * 8 + (lane & 3) * 2;
        float bx = sBias[c], by = sBias[c + 1];
        if (r0 < N_NODES) {
            float2 v0 = make_float2(acc[nt][0] + bx, acc[nt][1] + by);
            *(float2*)(out + (size_t)r0 * DIM + c) = v0;
        }
        if (r1 < N_NODES) {
            float2 v1 = make_float2(acc[nt][2] + bx, acc[nt][3] + by);
            *(float2*)(out + (size_t)r1 * DIM + c) = v1;
        }
    }
}

// ---------------------------------------------------------------------------
extern "C" void kernel_launch(void* const* d_in, const int* in_sizes, int n_in,
                              void* d_out, int out_size) {
    const float* x        = (const float*)d_in[0];
    const int*   ei       = (const int*)d_in[1];
    const float* W_self   = (const float*)d_in[2];
    const float* b_self   = (const float*)d_in[3];
    const float* W_neigh  = (const float*)d_in[4];
    const float* b_neigh  = (const float*)d_in[5];
    float*       out      = (float*)d_out;

    static void* cnt_ptr = nullptr;
    static void* ctl_ptr = nullptr;
    if (!cnt_ptr) {
        cudaGetSymbolAddress(&cnt_ptr, g_cnt);
        cudaGetSymbolAddress(&ctl_ptr, g_ctl);
        cudaFuncSetAttribute(hmma_kernel,
                             cudaFuncAttributeMaxDynamicSharedMemorySize,
                             HMMA_SMEM);
    }

    cudaMemsetAsync(cnt_ptr, 0, (size_t)N_NODES * sizeof(int));
    cudaMemsetAsync(ctl_ptr, 0, 2 * sizeof(int));

    prep_kernel<<<(PREP_TOTAL + 255) / 256, 256>>>(x, W_self, W_neigh, ei);
    gather_kernel<<<GATHER_BLOCKS, 192>>>(x);
    hmma_kernel<<<HMMA_BLOCKS, HMMA_THREADS, HMMA_SMEM>>>(b_self, b_neigh, out);
}

// round 17
// speedup vs baseline: 1.0313x; 1.0313x over previous
#include <cuda_runtime.h>
#include <cuda_fp16.h>
#include <cstdint>

#define N_NODES 50000
#define N_EDGES 800000
#define DIM 96
#define KTOT 192
#define CAP 64   // bucket capacity per node (avg degree 16)

// ---------------------------------------------------------------------------
// Scratch (__device__ globals per allocation-free rule)
// ---------------------------------------------------------------------------
__device__ __align__(128) __half g_ah[N_NODES * KTOT];  // [xh | mean_h], 19.2MB
__device__ __align__(128) __half g_wh[DIM * KTOT];      // B fp16 [n][k]
__device__ __align__(128) float g_agg[N_NODES * DIM];   // raw sums (ovf rows)
__device__ int g_cnt[N_NODES];
__device__ int g_bucket[N_NODES * CAP];                 // 12.8 MB
__device__ int g_ctl[2];                                // [0]=novf, [1]=done
__device__ int g_ovf[N_EDGES * 2];

// ---------------------------------------------------------------------------
// Convert x -> fp16 (g_ah cols 0..95) and [Ws|Wn] -> g_wh. One kernel.
// ---------------------------------------------------------------------------
#define NXH2 (N_NODES * 48)       // half2 items for x
#define NWH2 (DIM * 48)           // half2 items per weight matrix

__global__ void convert_kernel(const float* __restrict__ x,
                               const float* __restrict__ Ws,
                               const float* __restrict__ Wn) {
    int t = blockIdx.x * blockDim.x + threadIdx.x;
    if (t < NXH2) {
        int row = t / 48, j2 = t % 48;
        float2 v = ((const float2*)x)[t];
        ((__half2*)g_ah)[row * 96 + j2] = __floats2half2_rn(v.x, v.y);
    } else if (t < NXH2 + NWH2) {
        int u = t - NXH2;
        int j = u / 48, kp = u % 48;
        float2 a = ((const float2*)Ws)[u];
        float2 b = ((const float2*)Wn)[u];
        ((__half2*)g_wh)[j * 96 + kp]      = __floats2half2_rn(a.x, a.y);
        ((__half2*)g_wh)[j * 96 + 48 + kp] = __floats2half2_rn(b.x, b.y);
    }
}

// ---------------------------------------------------------------------------
// Fill: bucket the edges by destination.
// ---------------------------------------------------------------------------
__global__ void fill_kernel(const int* __restrict__ ei) {
    int e = blockIdx.x * blockDim.x + threadIdx.x;
    if (e >= N_EDGES) return;
    int src = __ldg(&ei[e]);
    int dst = __ldg(&ei[N_EDGES + e]);
    int slot = atomicAdd(&g_cnt[dst], 1);
    if (slot < CAP) {
        g_bucket[dst * CAP + slot] = src;
    } else {
        int o = atomicAdd(&g_ctl[0], 1);
        g_ovf[2 * o + 0] = src;
        g_ovf[2 * o + 1] = dst;
    }
}

// ---------------------------------------------------------------------------
// Gather: 24 threads/node (8 nodes per 192-thread block). Thread owns 4
// features; per neighbor one uint2 (4 fp16) load; bucket read via int4.
// Fast path (deg<=CAP): writes normalized fp16 mean directly to g_ah.
// Overflow rows: raw fp32 sums to g_agg; LAST finished block fixes them
// inline (no separate launch; usually zero work).
// ---------------------------------------------------------------------------
#define GATHER_BLOCKS ((N_NODES + 7) / 8)   // 6250

__global__ void gather_kernel(const float* __restrict__ x) {
    int node = blockIdx.x * 8 + (threadIdx.x / 24);
    int j4 = threadIdx.x % 24;          // uint2 (4-half) index 0..23

    if (node < N_NODES) {
        int deg = g_cnt[node];
        int n = (deg < CAP) ? deg : CAP;
        const int* __restrict__ b = g_bucket + node * CAP;
        const uint2* __restrict__ xh4 = (const uint2*)g_ah;   // row = 48 uint2

        float ax = 0.f, ay = 0.f, az = 0.f, aw = 0.f;
        int s = 0;
        for (; s + 4 <= n; s += 4) {
            int4 b4 = __ldg((const int4*)(b + s));
            uint2 v0 = __ldg(&xh4[b4.x * 48 + j4]);
            uint2 v1 = __ldg(&xh4[b4.y * 48 + j4]);
            uint2 v2 = __ldg(&xh4[b4.z * 48 + j4]);
            uint2 v3 = __ldg(&xh4[b4.w * 48 + j4]);
            float2 p0 = __half22float2(*(__half2*)&v0.x);
            float2 q0 = __half22float2(*(__half2*)&v0.y);
            float2 p1 = __half22float2(*(__half2*)&v1.x);
            float2 q1 = __half22float2(*(__half2*)&v1.y);
            float2 p2 = __half22float2(*(__half2*)&v2.x);
            float2 q2 = __half22float2(*(__half2*)&v2.y);
            float2 p3 = __half22float2(*(__half2*)&v3.x);
            float2 q3 = __half22float2(*(__half2*)&v3.y);
            ax += (p0.x + p1.x) + (p2.x + p3.x);
            ay += (p0.y + p1.y) + (p2.y + p3.y);
            az += (q0.x + q1.x) + (q2.x + q3.x);
            aw += (q0.y + q1.y) + (q2.y + q3.y);
        }
        for (; s < n; s++) {
            int sn = __ldg(&b[s]);
            uint2 v = __ldg(&xh4[sn * 48 + j4]);
            float2 p = __half22float2(*(__half2*)&v.x);
            float2 q = __half22float2(*(__half2*)&v.y);
            ax += p.x; ay += p.y; az += q.x; aw += q.y;
        }

        if (deg <= CAP) {
            float inv = 1.0f / (float)((deg > 1) ? deg : 1);
            __half2 h0 = __floats2half2_rn(ax * inv, ay * inv);
            __half2 h1 = __floats2half2_rn(az * inv, aw * inv);
            uint2 o;
            o.x = *(uint32_t*)&h0;
            o.y = *(uint32_t*)&h1;
            ((uint2*)g_ah)[node * 48 + 24 + j4] = o;
        } else {
            float4 o = make_float4(ax, ay, az, aw);
            ((float4*)g_agg)[node * 24 + j4] = o;
        }
    }

    // ---- last-block-done overflow fix (usually zero work) ----
    __shared__ int sIsLast;
    __threadfence();
    __syncthreads();
    if (threadIdx.x == 0) {
        int done = atomicAdd(&g_ctl[1], 1);
        sIsLast = (done == GATHER_BLOCKS - 1) ? 1 : 0;
    }
    __syncthreads();
    if (!sIsLast) return;

    int nov = g_ctl[0];
    if (nov == 0) return;
    int total = nov * 24;
    for (int t = threadIdx.x; t < total; t += blockDim.x) {
        int e = t / 24, c = t % 24;
        int src = g_ovf[2 * e + 0];
        int dst = g_ovf[2 * e + 1];
        float4 v = ((const float4*)(x + (size_t)src * DIM))[c];
        float* p = g_agg + (size_t)dst * DIM + c * 4;
        asm volatile("red.global.add.v4.f32 [%0], {%1,%2,%3,%4};"
                     :: "l"(p), "f"(v.x), "f"(v.y), "f"(v.z), "f"(v.w)
                     : "memory");
    }
    __threadfence();
    __syncthreads();
    for (int t = threadIdx.x; t < total; t += blockDim.x) {
        int e = t / 24, c = t % 24;
        int dst = g_ovf[2 * e + 1];
        float inv = 1.0f / (float)g_cnt[dst];
        float4 v = ((const float4*)g_agg)[dst * 24 + c];
        __half2 h0 = __floats2half2_rn(v.x * inv, v.y * inv);
        __half2 h1 = __floats2half2_rn(v.z * inv, v.w * inv);
        uint2 o;
        o.x = *(uint32_t*)&h0;
        o.y = *(uint32_t*)&h1;
        ((uint2*)g_ah)[dst * 48 + 24 + c] = o;
    }
}

// ---------------------------------------------------------------------------
// HMMA GEMM (round-15 proven config): out = g_ah @ g_wh^T + (bs+bn)
// BM=128 rows/block, 4 warps (128 threads); warp = 32 rows x 96 cols
// = 2x12 m16n8k16 tiles. Smem pitch 200 halves -> conflict-free ldmatrix.
// ---------------------------------------------------------------------------
#define HBM 128
#define HPITCH 200
#define HMMA_THREADS 128
#define HMMA_BLOCKS ((N_NODES + HBM - 1) / HBM)   // 391
#define HMMA_SMEM ((HBM + DIM) * HPITCH * 2)      // 89600 bytes

__device__ __forceinline__ uint32_t smem_u32(const void* p) {
    return (uint32_t)__cvta_generic_to_shared(p);
}
__device__ __forceinline__ void ldsm_x4(uint32_t& r0, uint32_t& r1,
                                        uint32_t& r2, uint32_t& r3,
                                        uint32_t addr) {
    asm volatile("ldmatrix.sync.aligned.m8n8.x4.shared.b16 {%0,%1,%2,%3}, [%4];"
                 : "=r"(r0), "=r"(r1), "=r"(r2), "=r"(r3) : "r"(addr));
}
__device__ __forceinline__ void mma16816(float* d, const uint32_t* a,
                                         const uint32_t* b) {
    asm volatile(
        "mma.sync.aligned.m16n8k16.row.col.f32.f16.f16.f32 "
        "{%0,%1,%2,%3}, {%4,%5,%6,%7}, {%8,%9}, {%0,%1,%2,%3};"
        : "+f"(d[0]), "+f"(d[1]), "+f"(d[2]), "+f"(d[3])
        : "r"(a[0]), "r"(a[1]), "r"(a[2]), "r"(a[3]), "r"(b[0]), "r"(b[1]));
}

__global__ __launch_bounds__(HMMA_THREADS)
void hmma_kernel(const float* __restrict__ bs, const float* __restrict__ bn,
                 float* __restrict__ out) {
    extern __shared__ __half hsm[];
    __half* sA = hsm;                      // [HBM][HPITCH]
    __half* sB = hsm + HBM * HPITCH;       // [DIM][HPITCH]
    __shared__ float sBias[DIM];

    const int tid = threadIdx.x;
    const int warp = tid >> 5;
    const int lane = tid & 31;
    const int rowBase = blockIdx.x * HBM;

    if (tid < DIM) sBias[tid] = bs[tid] + bn[tid];

    #pragma unroll
    for (int it = 0; it < 24; it++) {
        int idx = it * HMMA_THREADS + tid;
        int m = idx / 24, q = idx % 24;
        int row = rowBase + m;
        uint4 v = make_uint4(0u, 0u, 0u, 0u);
        if (row < N_NODES)
            v = ((const uint4*)(g_ah + (size_t)row * KTOT))[q];
        *(uint4*)&sA[m * HPITCH + q * 8] = v;
    }
    #pragma unroll
    for (int it = 0; it < 18; it++) {
        int idx = it * HMMA_THREADS + tid;
        int j = idx / 24, q = idx % 24;
        *(uint4*)&sB[j * HPITCH + q * 8] = ((const uint4*)(g_wh + j * KTOT))[q];
    }
    __syncthreads();

    float acc[2][12][4];
    #pragma unroll
    for (int mt = 0; mt < 2; mt++)
        #pragma unroll
        for (int nt = 0; nt < 12; nt++)
            #pragma unroll
            for (int i = 0; i < 4; i++) acc[mt][nt][i] = 0.0f;

    const int mrow0 = warp * 32;

    #pragma unroll 3
    for (int k16 = 0; k16 < KTOT / 16; k16++) {
        int k0 = k16 * 16;
        uint32_t a[2][4];
        #pragma unroll
        for (int mt = 0; mt < 2; mt++) {
            uint32_t addr = smem_u32(
                &sA[(mrow0 + mt * 16 + (lane & 15)) * HPITCH +
                    k0 + ((lane >> 4) << 3)]);
            ldsm_x4(a[mt][0], a[mt][1], a[mt][2], a[mt][3], addr);
        }
        uint32_t b[12][2];
        #pragma unroll
        for (int np = 0; np < 6; np++) {
            int n0 = np * 16;
            int nrow = n0 + ((lane >> 4) << 3) + (lane & 7);
            int kcol = k0 + (((lane >> 3) & 1) << 3);
            uint32_t addr = smem_u32(&sB[nrow * HPITCH + kcol]);
            uint32_t r0, r1, r2, r3;
            ldsm_x4(r0, r1, r2, r3, addr);
            b[2 * np + 0][0] = r0; b[2 * np + 0][1] = r1;
            b[2 * np + 1][0] = r2; b[2 * np + 1][1] = r3;
        }
        #pragma unroll
        for (int mt = 0; mt < 2; mt++)
            #pragma unroll
            for (int nt = 0; nt < 12; nt++)
                mma16816(acc[mt][nt], a[mt], b[nt]);
    }

    #pragma unroll
    for (int mt = 0; mt < 2; mt++) {
        int r0 = rowBase + mrow0 + mt * 16 + (lane >> 2);
        #pragma unroll
        for (int nt = 0; nt < 12; nt++) {
            int c = nt * 8 + (lane & 3) * 2;
            float bx = sBias[c], by = sBias[c + 1];
            if (r0 < N_NODES) {
                float2 v0 = make_float2(acc[mt][nt][0] + bx,
                                        acc[mt][nt][1] + by);
                *(float2*)(out + (size_t)r0 * DIM + c) = v0;
            }
            int r1 = r0 + 8;
            if (r1 < N_NODES) {
                float2 v1 = make_float2(acc[mt][nt][2] + bx,
                                        acc[mt][nt][3] + by);
                *(float2*)(out + (size_t)r1 * DIM + c) = v1;
            }
        }
    }
}

// ---------------------------------------------------------------------------
extern "C" void kernel_launch(void* const* d_in, const int* in_sizes, int n_in,
                              void* d_out, int out_size) {
    const float* x        = (const float*)d_in[0];
    const int*   ei       = (const int*)d_in[1];
    const float* W_self   = (const float*)d_in[2];
    const float* b_self   = (const float*)d_in[3];
    const float* W_neigh  = (const float*)d_in[4];
    const float* b_neigh  = (const float*)d_in[5];
    float*       out      = (float*)d_out;

    static void* cnt_ptr = nullptr;
    static void* ctl_ptr = nullptr;
    if (!cnt_ptr) {
        cudaGetSymbolAddress(&cnt_ptr, g_cnt);
        cudaGetSymbolAddress(&ctl_ptr, g_ctl);
        cudaFuncSetAttribute(hmma_kernel,
                             cudaFuncAttributeMaxDynamicSharedMemorySize,
                             HMMA_SMEM);
    }

    cudaMemsetAsync(cnt_ptr, 0, (size_t)N_NODES * sizeof(int));
    cudaMemsetAsync(ctl_ptr, 0, 2 * sizeof(int));

    convert_kernel<<<(NXH2 + NWH2 + 255) / 256, 256>>>(x, W_self, W_neigh);
    fill_kernel<<<(N_EDGES + 255) / 256, 256>>>(ei);
    gather_kernel<<<GATHER_BLOCKS, 192>>>(x);
    hmma_kernel<<<HMMA_BLOCKS, HMMA_THREADS, HMMA_SMEM>>>(b_self, b_neigh, out);
}